// round 15
// baseline (speedup 1.0000x reference)
#include <cuda_runtime.h>
#include <cuda_fp16.h>
#include <cstdint>

#define N_NODES 100000
#define HID 128
#define CAP 64            // bucket capacity (Poisson(16) max-degree << 64)

// Scratch (no cudaMalloc allowed)
__device__ __half g_bufh[N_NODES * HID];   // layer-1 pre-scaled rows (fp16)
__device__ __half g_aggh[N_NODES * HID];   // layer-1 output rows (fp16)
__device__ __half g_a2h [N_NODES * HID];   // layer-2 GEMM input (fp16)
__device__ int    g_cur [N_NODES];         // degree counter / fill cursor
__device__ int    g_csr [N_NODES * CAP];   // bucketed src ids

// ---------------------------------------------------------------- CSR (buckets)
__global__ void k_zero_cur(int n) {
    int i = blockIdx.x * blockDim.x + threadIdx.x;
    if (i < n) g_cur[i] = 0;
}
__global__ void k_fill(const int* __restrict__ src, const int* __restrict__ dst, int E) {
    int i = blockIdx.x * blockDim.x + threadIdx.x;
    int b = i * 4;
    if (b + 4 <= E) {
        int4 d4 = *(const int4*)(dst + b);
        int4 s4 = *(const int4*)(src + b);
        int p;
        p = atomicAdd(&g_cur[d4.x], 1); if (p < CAP) g_csr[d4.x * CAP + p] = s4.x;
        p = atomicAdd(&g_cur[d4.y], 1); if (p < CAP) g_csr[d4.y * CAP + p] = s4.y;
        p = atomicAdd(&g_cur[d4.z], 1); if (p < CAP) g_csr[d4.z * CAP + p] = s4.z;
        p = atomicAdd(&g_cur[d4.w], 1); if (p < CAP) g_csr[d4.w * CAP + p] = s4.w;
    } else {
        for (int e = b; e < E; e++) {
            int d = dst[e];
            int p = atomicAdd(&g_cur[d], 1);
            if (p < CAP) g_csr[d * CAP + p] = src[e];
        }
    }
}

// ---------------------------------------------------------------- helpers
__device__ __forceinline__ uint32_t pk(float lo, float hi) {
    uint32_t u;
    asm("cvt.rn.f16x2.f32 %0, %1, %2;" : "=r"(u) : "f"(hi), "f"(lo));
    return u;
}
__device__ __forceinline__ void mma_f16(float c[4], const uint32_t a[4], const uint32_t b[2]) {
    asm volatile(
        "mma.sync.aligned.m16n8k16.row.col.f32.f16.f16.f32 "
        "{%0,%1,%2,%3}, {%4,%5,%6,%7}, {%8,%9}, {%0,%1,%2,%3};"
        : "+f"(c[0]), "+f"(c[1]), "+f"(c[2]), "+f"(c[3])
        : "r"(a[0]), "r"(a[1]), "r"(a[2]), "r"(a[3]), "r"(b[0]), "r"(b[1]));
}
__device__ __forceinline__ uint32_t s2u(const void* p) {
    return (uint32_t)__cvta_generic_to_shared(p);
}
__device__ __forceinline__ void cpa16(uint32_t dst, const void* src, int srcsize) {
    asm volatile("cp.async.cg.shared.global [%0], [%1], 16, %2;\n"
                 :: "r"(dst), "l"(src), "r"(srcsize));
}
#define CP_COMMIT() asm volatile("cp.async.commit_group;\n" ::: "memory")
#define CP_WAIT2()  asm volatile("cp.async.wait_group 2;\n" ::: "memory")

// packed f32x2 helpers (Blackwell)
__device__ __forceinline__ uint64_t pk2f(float x, float y) {
    uint64_t r;
    asm("mov.b64 %0, {%1, %2};" : "=l"(r) : "f"(x), "f"(y));
    return r;
}
__device__ __forceinline__ void unpk2f(uint64_t v, float& x, float& y) {
    asm("mov.b64 {%0, %1}, %2;" : "=f"(x), "=f"(y) : "l"(v));
}
__device__ __forceinline__ uint64_t addx2(uint64_t a, uint64_t b) {
    uint64_t r;
    asm("add.rn.f32x2 %0, %1, %2;" : "=l"(r) : "l"(a), "l"(b));
    return r;
}

#define KC    16
#define APAD  20     // fp32 A row pad (floats)
#define AHPAD 24     // fp16 A row pad (halves)
#define BPAD  132    // conflict-free for k16 B frag pattern

// ---------------------------------------------------------------- GEMM 1
// 64x128 tile, 256 thr (8 warps 2m x 4n), fp16 mma, 4-stage cp.async, 3 CTA/SM
__global__ void __launch_bounds__(256, 3)
k_gemm1(const float* __restrict__ A, const float* __restrict__ W, int M) {
    const int K = 256;
    const int NS = K / KC;                  // 16
    extern __shared__ __align__(16) char dsm[];
    float (*As)[64][APAD] = (float (*)[64][APAD])dsm;                        // 4 stages
    float (*Bs)[KC][BPAD] = (float (*)[KC][BPAD])(dsm + 4 * 64 * APAD * 4);
    int tid = threadIdx.x;
    int lane = tid & 31;
    int warp = tid >> 5;
    int wm = warp >> 2;             // 0..1
    int wn = warp & 3;              // 0..3
    int block_row = blockIdx.x * 64;
    int t4 = lane >> 2;             // 0..7
    int tk = lane & 3;              // 0..3

    float acc[2][4][4];
#pragma unroll
    for (int i = 0; i < 2; i++)
#pragma unroll
        for (int j = 0; j < 4; j++)
#pragma unroll
            for (int c = 0; c < 4; c++) acc[i][j][c] = 0.f;

    int a_row = tid >> 2;           // 0..63, 4 threads/row
    int a_k   = (tid & 3) * 4;      // 0/4/8/12 (floats)
    int b_row = tid >> 4;           // 0..15
    int b_col = (tid & 15) * 8;     // 0..120
    int gr = block_row + a_row;
    int a_size = (gr < M) ? 16 : 0;
    const float* agp = &A[(long)gr * K + a_k];

    auto issue = [&](int s) {
        int buf = s & 3;
        int k0 = s * KC;
        cpa16(s2u(&As[buf][a_row][a_k]), agp + k0, a_size);
        const float* wp = &W[(k0 + b_row) * 128 + b_col];
        cpa16(s2u(&Bs[buf][b_row][b_col]),     wp,     16);
        cpa16(s2u(&Bs[buf][b_row][b_col + 4]), wp + 4, 16);
    };

    issue(0); CP_COMMIT();
    issue(1); CP_COMMIT();
    issue(2); CP_COMMIT();

    for (int s = 0; s < NS; s++) {
        CP_WAIT2();              // stage s arrived (s+1, s+2 may be in flight)
        __syncthreads();
        if (s + 3 < NS) issue(s + 3);
        CP_COMMIT();

        int buf = s & 3;
        uint32_t afr[2][4];
#pragma unroll
        for (int mt = 0; mt < 2; mt++) {
            int r0 = wm * 32 + mt * 16 + t4;
            float2 x0 = *(const float2*)&As[buf][r0    ][2 * tk];
            float2 x1 = *(const float2*)&As[buf][r0 + 8][2 * tk];
            float2 x2 = *(const float2*)&As[buf][r0    ][2 * tk + 8];
            float2 x3 = *(const float2*)&As[buf][r0 + 8][2 * tk + 8];
            afr[mt][0] = pk(x0.x, x0.y);
            afr[mt][1] = pk(x1.x, x1.y);
            afr[mt][2] = pk(x2.x, x2.y);
            afr[mt][3] = pk(x3.x, x3.y);
        }
        uint32_t bfr[4][2];
#pragma unroll
        for (int nt = 0; nt < 4; nt++) {
            int c0 = wn * 32 + nt * 8 + t4;
            bfr[nt][0] = pk(Bs[buf][2 * tk    ][c0], Bs[buf][2 * tk + 1][c0]);
            bfr[nt][1] = pk(Bs[buf][2 * tk + 8][c0], Bs[buf][2 * tk + 9][c0]);
        }
#pragma unroll
        for (int mt = 0; mt < 2; mt++)
#pragma unroll
            for (int nt = 0; nt < 4; nt++)
                mma_f16(acc[mt][nt], afr[mt], bfr[nt]);
    }

#pragma unroll
    for (int mt = 0; mt < 2; mt++) {
        int r0 = block_row + wm * 32 + mt * 16 + t4;
        int r1 = r0 + 8;
        float s0 = (r0 < M) ? rsqrtf((float)(g_cur[r0] + 1)) : 0.f;
        float s1 = (r1 < M) ? rsqrtf((float)(g_cur[r1] + 1)) : 0.f;
#pragma unroll
        for (int nt = 0; nt < 4; nt++) {
            int col = wn * 32 + nt * 8 + tk * 2;
            if (r0 < M)
                *(__half2*)&g_bufh[(long)r0 * 128 + col] =
                    __float22half2_rn(make_float2(acc[mt][nt][0] * s0, acc[mt][nt][1] * s0));
            if (r1 < M)
                *(__half2*)&g_bufh[(long)r1 * 128 + col] =
                    __float22half2_rn(make_float2(acc[mt][nt][2] * s1, acc[mt][nt][3] * s1));
        }
    }
}

// ---------------------------------------------------------------- gather
// warp per node, fp16 rows (8 B/lane), independent loads, packed f32x2 accumulate
// (two accumulator banks break the serial add chain; no load pairing).
// MODE=1: g_bufh -> g_aggh, out = fp16(relu(dinv*acc + b)*dinv)
// MODE=0: g_aggh -> g_a2h (fp16), out = dinv*acc
template <int MODE>
__global__ void k_gather(const float* __restrict__ bias, int n) {
    const __half* __restrict__ in = MODE ? g_bufh : g_aggh;
    int w = (blockIdx.x * blockDim.x + threadIdx.x) >> 5;
    int lane = threadIdx.x & 31;
    if (w >= n) return;
    int start = w * CAP;
    int raw = g_cur[w];
    int cnt = min(raw, CAP);
    float s = rsqrtf((float)(raw + 1));
    long col = (long)lane * 4;

    uint2 sv = *(const uint2*)&in[(long)w * 128 + col];   // self loop
    float2 f0 = __half22float2(*(__half2*)&sv.x);
    float2 f1 = __half22float2(*(__half2*)&sv.y);
    uint64_t aA = pk2f(f0.x, f0.y), bA = pk2f(f1.x, f1.y);   // bank A
    uint64_t aB = pk2f(0.f, 0.f),   bB = pk2f(0.f, 0.f);     // bank B

    int j = 0;
    for (; j + 8 <= cnt; j += 8) {
        int4 i0 = *(const int4*)&g_csr[start + j];
        int4 i1 = *(const int4*)&g_csr[start + j + 4];
        uint2 v[8];
        v[0] = __ldg((const uint2*)&in[(long)i0.x * 128 + col]);
        v[1] = __ldg((const uint2*)&in[(long)i0.y * 128 + col]);
        v[2] = __ldg((const uint2*)&in[(long)i0.z * 128 + col]);
        v[3] = __ldg((const uint2*)&in[(long)i0.w * 128 + col]);
        v[4] = __ldg((const uint2*)&in[(long)i1.x * 128 + col]);
        v[5] = __ldg((const uint2*)&in[(long)i1.y * 128 + col]);
        v[6] = __ldg((const uint2*)&in[(long)i1.z * 128 + col]);
        v[7] = __ldg((const uint2*)&in[(long)i1.w * 128 + col]);
#pragma unroll
        for (int u = 0; u < 8; u++) {
            float2 x = __half22float2(*(__half2*)&v[u].x);
            float2 y = __half22float2(*(__half2*)&v[u].y);
            if (u & 1) { aB = addx2(aB, pk2f(x.x, x.y)); bB = addx2(bB, pk2f(y.x, y.y)); }
            else       { aA = addx2(aA, pk2f(x.x, x.y)); bA = addx2(bA, pk2f(y.x, y.y)); }
        }
    }
    for (; j < cnt; j++) {
        int sIdx = g_csr[start + j];
        uint2 v = __ldg((const uint2*)&in[(long)sIdx * 128 + col]);
        float2 x = __half22float2(*(__half2*)&v.x);
        float2 y = __half22float2(*(__half2*)&v.y);
        aA = addx2(aA, pk2f(x.x, x.y));
        bA = addx2(bA, pk2f(y.x, y.y));
    }

    aA = addx2(aA, aB);
    bA = addx2(bA, bB);
    float4 acc;
    unpk2f(aA, acc.x, acc.y);
    unpk2f(bA, acc.z, acc.w);

    uint2 o;
    if (MODE) {
        float4 bb = __ldg((const float4*)&bias[col]);
        float4 r;
        r.x = fmaxf(fmaf(s, acc.x, bb.x), 0.f) * s;
        r.y = fmaxf(fmaf(s, acc.y, bb.y), 0.f) * s;
        r.z = fmaxf(fmaf(s, acc.z, bb.z), 0.f) * s;
        r.w = fmaxf(fmaf(s, acc.w, bb.w), 0.f) * s;
        *(__half2*)&o.x = __float22half2_rn(make_float2(r.x, r.y));
        *(__half2*)&o.y = __float22half2_rn(make_float2(r.z, r.w));
        *(uint2*)&g_aggh[(long)w * 128 + col] = o;
    } else {
        *(__half2*)&o.x = __float22half2_rn(make_float2(acc.x * s, acc.y * s));
        *(__half2*)&o.y = __float22half2_rn(make_float2(acc.z * s, acc.w * s));
        *(uint2*)&g_a2h[(long)w * 128 + col] = o;
    }
}

// ---------------------------------------------------------------- GEMM 2
// 64x128 tile, fp16 mma, A fp16, 4-stage cp.async, 3 CTA/SM
// out_mu = a2 @ Wmu + bmu ; out_lv = a2 @ Wlv + blv   (a2 = g_a2h, pre-scaled)
__global__ void __launch_bounds__(256, 3)
k_gemm2(const float* __restrict__ Wmu, const float* __restrict__ Wlv,
        const float* __restrict__ bmu, const float* __restrict__ blv,
        float* __restrict__ out, int M) {
    const int K = 128;
    const int NS = K / KC;                  // 8
    __shared__ __half Ah[4][64][AHPAD];
    __shared__ float  Bs[4][KC][BPAD];
    __shared__ float  bias[128];
    int tid = threadIdx.x;
    int lane = tid & 31;
    int warp = tid >> 5;
    int wm = warp >> 2;             // 0..1
    int wn = warp & 3;              // 0..3
    int block_row = blockIdx.x * 64;
    int t4 = lane >> 2;
    int tk = lane & 3;

    if (tid < 128) bias[tid] = (tid < 64) ? bmu[tid] : blv[tid - 64];

    float acc[2][4][4];
#pragma unroll
    for (int i = 0; i < 2; i++)
#pragma unroll
        for (int j = 0; j < 4; j++)
#pragma unroll
            for (int c = 0; c < 4; c++) acc[i][j][c] = 0.f;

    int a_row = tid >> 1;           // 0..127 (only tid<128 used)
    int a_k   = (tid & 1) * 8;      // halves: 0 / 8 (16 B per thread)
    int b_row = tid >> 4;           // 0..15
    int b_col = (tid & 15) * 8;     // 0..120
    int gr = block_row + a_row;
    int a_size = (tid < 128 && gr < M) ? 16 : 0;
    const __half* agp = &g_a2h[(long)gr * K + a_k];
    const float* wbase = (b_col < 64) ? (Wmu + b_col) : (Wlv + (b_col - 64));

    auto issue = [&](int s) {
        int buf = s & 3;
        int k0 = s * KC;
        if (tid < 128) cpa16(s2u(&Ah[buf][a_row][a_k]), agp + k0, a_size);
        const float* wp = wbase + (long)(k0 + b_row) * 64;
        cpa16(s2u(&Bs[buf][b_row][b_col]),     wp,     16);
        cpa16(s2u(&Bs[buf][b_row][b_col + 4]), wp + 4, 16);
    };

    issue(0); CP_COMMIT();
    issue(1); CP_COMMIT();
    issue(2); CP_COMMIT();

    for (int s = 0; s < NS; s++) {
        CP_WAIT2();
        __syncthreads();
        if (s + 3 < NS) issue(s + 3);
        CP_COMMIT();

        int buf = s & 3;
        uint32_t afr[2][4];
#pragma unroll
        for (int mt = 0; mt < 2; mt++) {
            int r0 = wm * 32 + mt * 16 + t4;
            afr[mt][0] = *(const uint32_t*)&Ah[buf][r0    ][2 * tk];
            afr[mt][1] = *(const uint32_t*)&Ah[buf][r0 + 8][2 * tk];
            afr[mt][2] = *(const uint32_t*)&Ah[buf][r0    ][2 * tk + 8];
            afr[mt][3] = *(const uint32_t*)&Ah[buf][r0 + 8][2 * tk + 8];
        }
        uint32_t bfr[4][2];
#pragma unroll
        for (int nt = 0; nt < 4; nt++) {
            int c0 = wn * 32 + nt * 8 + t4;
            bfr[nt][0] = pk(Bs[buf][2 * tk    ][c0], Bs[buf][2 * tk + 1][c0]);
            bfr[nt][1] = pk(Bs[buf][2 * tk + 8][c0], Bs[buf][2 * tk + 9][c0]);
        }
#pragma unroll
        for (int mt = 0; mt < 2; mt++)
#pragma unroll
            for (int nt = 0; nt < 4; nt++)
                mma_f16(acc[mt][nt], afr[mt], bfr[nt]);
    }

    // epilogue: col<64 -> mu at out[r*64+col], else logvar at out[M*64 + r*64 + col-64]
    long lv_base = (long)M * 64;
#pragma unroll
    for (int mt = 0; mt < 2; mt++) {
        int r0 = block_row + wm * 32 + mt * 16 + t4;
        int r1 = r0 + 8;
#pragma unroll
        for (int nt = 0; nt < 4; nt++) {
            int col = wn * 32 + nt * 8 + tk * 2;
            float b0 = bias[col];
            float b1 = bias[col + 1];
            long off = (col < 64) ? (long)col : lv_base + (col - 64);
            if (r0 < M)
                *(float2*)&out[(long)r0 * 64 + off] =
                    make_float2(acc[mt][nt][0] + b0, acc[mt][nt][1] + b1);
            if (r1 < M)
                *(float2*)&out[(long)r1 * 64 + off] =
                    make_float2(acc[mt][nt][2] + b0, acc[mt][nt][3] + b1);
        }
    }
}

// ---------------------------------------------------------------- launch
extern "C" void kernel_launch(void* const* d_in, const int* in_sizes, int n_in,
                              void* d_out, int out_size) {
    const float* x   = (const float*)d_in[0];
    const int*   ei  = (const int*)d_in[1];   // JAX default x64 off: int32
    const float* W1  = (const float*)d_in[2];
    const float* b1  = (const float*)d_in[3];
    const float* Wmu = (const float*)d_in[4];
    const float* bmu = (const float*)d_in[5];
    const float* Wlv = (const float*)d_in[6];
    const float* blv = (const float*)d_in[7];
    float* out = (float*)d_out;

    int n = in_sizes[0] / 256;
    int E = in_sizes[1] / 2;
    const int* src = ei;
    const int* dst = ei + E;

    int nb_n = (n + 255) / 256;
    int nb_e4 = ((E + 3) / 4 + 255) / 256;   // 4 edges per thread
    int nb_g1 = (n + 63) / 64;               // 64-row tiles
    int nb_w = (n * 32 + 255) / 256;         // warp per node

    // dynamic smem for GEMM1 (4-stage ring: 54,272 B)
    const int g1_smem = 4 * (64 * APAD * 4 + KC * BPAD * 4);
    static bool attr_set = false;
    if (!attr_set) {
        cudaFuncSetAttribute(k_gemm1, cudaFuncAttributeMaxDynamicSharedMemorySize, g1_smem);
        attr_set = true;
    }

    // bucketed CSR (no scan, dinv computed inline by consumers)
    k_zero_cur<<<nb_n, 256>>>(n);
    k_fill    <<<nb_e4, 256>>>(src, dst, E);

    // layer 1
    k_gemm1   <<<nb_g1, 256, g1_smem>>>(x, W1, n);
    k_gather<1><<<nb_w, 256>>>(b1, n);
    // layer 2 (shared aggregation for mu/logvar)
    k_gather<0><<<nb_w, 256>>>(b1, n);
    k_gemm2   <<<nb_g1, 256>>>(Wmu, Wlv, bmu, blv, out, n);
}

// round 16
// speedup vs baseline: 1.2737x; 1.2737x over previous
#include <cuda_runtime.h>
#include <cuda_fp16.h>
#include <cstdint>

#define N_NODES 100000
#define HID 128
#define CAP 64            // bucket capacity (Poisson(16) max-degree << 64)

// Scratch (no cudaMalloc allowed)
__device__ __half g_bufh[N_NODES * HID];   // layer-1 pre-scaled rows (fp16)
__device__ __half g_aggh[N_NODES * HID];   // layer-1 output rows (fp16)
__device__ __half g_a2h [N_NODES * HID];   // layer-2 GEMM input (fp16)
__device__ int    g_cur [N_NODES];         // degree counter / fill cursor
__device__ int    g_csr [N_NODES * CAP];   // bucketed src ids

// ---------------------------------------------------------------- CSR (buckets)
__global__ void k_zero_cur(int n) {
    int i = blockIdx.x * blockDim.x + threadIdx.x;
    if (i < n) g_cur[i] = 0;
}
__global__ void k_fill(const int* __restrict__ src, const int* __restrict__ dst, int E) {
    int i = blockIdx.x * blockDim.x + threadIdx.x;
    int b = i * 4;
    if (b + 4 <= E) {
        int4 d4 = *(const int4*)(dst + b);
        int4 s4 = *(const int4*)(src + b);
        int p;
        p = atomicAdd(&g_cur[d4.x], 1); if (p < CAP) g_csr[d4.x * CAP + p] = s4.x;
        p = atomicAdd(&g_cur[d4.y], 1); if (p < CAP) g_csr[d4.y * CAP + p] = s4.y;
        p = atomicAdd(&g_cur[d4.z], 1); if (p < CAP) g_csr[d4.z * CAP + p] = s4.z;
        p = atomicAdd(&g_cur[d4.w], 1); if (p < CAP) g_csr[d4.w * CAP + p] = s4.w;
    } else {
        for (int e = b; e < E; e++) {
            int d = dst[e];
            int p = atomicAdd(&g_cur[d], 1);
            if (p < CAP) g_csr[d * CAP + p] = src[e];
        }
    }
}

// ---------------------------------------------------------------- helpers
__device__ __forceinline__ uint32_t pk(float lo, float hi) {
    uint32_t u;
    asm("cvt.rn.f16x2.f32 %0, %1, %2;" : "=r"(u) : "f"(hi), "f"(lo));
    return u;
}
__device__ __forceinline__ void mma_f16(float c[4], const uint32_t a[4], const uint32_t b[2]) {
    asm volatile(
        "mma.sync.aligned.m16n8k16.row.col.f32.f16.f16.f32 "
        "{%0,%1,%2,%3}, {%4,%5,%6,%7}, {%8,%9}, {%0,%1,%2,%3};"
        : "+f"(c[0]), "+f"(c[1]), "+f"(c[2]), "+f"(c[3])
        : "r"(a[0]), "r"(a[1]), "r"(a[2]), "r"(a[3]), "r"(b[0]), "r"(b[1]));
}
__device__ __forceinline__ uint32_t s2u(const void* p) {
    return (uint32_t)__cvta_generic_to_shared(p);
}
__device__ __forceinline__ void cpa16(uint32_t dst, const void* src, int srcsize) {
    asm volatile("cp.async.cg.shared.global [%0], [%1], 16, %2;\n"
                 :: "r"(dst), "l"(src), "r"(srcsize));
}
#define CP_COMMIT() asm volatile("cp.async.commit_group;\n" ::: "memory")
#define CP_WAIT2()  asm volatile("cp.async.wait_group 2;\n" ::: "memory")

#define KC    16
#define APAD  20     // fp32 A row pad (floats)
#define AHPAD 24     // fp16 A row pad (halves)
#define BPAD  132    // conflict-free for k16 B frag pattern

// ---------------------------------------------------------------- GEMM 1
// 64x128 tile, 256 thr (8 warps 2m x 4n), fp16 mma, 4-stage cp.async, 3 CTA/SM
__global__ void __launch_bounds__(256, 3)
k_gemm1(const float* __restrict__ A, const float* __restrict__ W, int M) {
    const int K = 256;
    const int NS = K / KC;                  // 16
    extern __shared__ __align__(16) char dsm[];
    float (*As)[64][APAD] = (float (*)[64][APAD])dsm;                        // 4 stages
    float (*Bs)[KC][BPAD] = (float (*)[KC][BPAD])(dsm + 4 * 64 * APAD * 4);
    int tid = threadIdx.x;
    int lane = tid & 31;
    int warp = tid >> 5;
    int wm = warp >> 2;             // 0..1
    int wn = warp & 3;              // 0..3
    int block_row = blockIdx.x * 64;
    int t4 = lane >> 2;             // 0..7
    int tk = lane & 3;              // 0..3

    float acc[2][4][4];
#pragma unroll
    for (int i = 0; i < 2; i++)
#pragma unroll
        for (int j = 0; j < 4; j++)
#pragma unroll
            for (int c = 0; c < 4; c++) acc[i][j][c] = 0.f;

    int a_row = tid >> 2;           // 0..63, 4 threads/row
    int a_k   = (tid & 3) * 4;      // 0/4/8/12 (floats)
    int b_row = tid >> 4;           // 0..15
    int b_col = (tid & 15) * 8;     // 0..120
    int gr = block_row + a_row;
    int a_size = (gr < M) ? 16 : 0;
    const float* agp = &A[(long)gr * K + a_k];

    auto issue = [&](int s) {
        int buf = s & 3;
        int k0 = s * KC;
        cpa16(s2u(&As[buf][a_row][a_k]), agp + k0, a_size);
        const float* wp = &W[(k0 + b_row) * 128 + b_col];
        cpa16(s2u(&Bs[buf][b_row][b_col]),     wp,     16);
        cpa16(s2u(&Bs[buf][b_row][b_col + 4]), wp + 4, 16);
    };

    issue(0); CP_COMMIT();
    issue(1); CP_COMMIT();
    issue(2); CP_COMMIT();

    for (int s = 0; s < NS; s++) {
        CP_WAIT2();              // stage s arrived (s+1, s+2 may be in flight)
        __syncthreads();
        if (s + 3 < NS) issue(s + 3);
        CP_COMMIT();

        int buf = s & 3;
        uint32_t afr[2][4];
#pragma unroll
        for (int mt = 0; mt < 2; mt++) {
            int r0 = wm * 32 + mt * 16 + t4;
            float2 x0 = *(const float2*)&As[buf][r0    ][2 * tk];
            float2 x1 = *(const float2*)&As[buf][r0 + 8][2 * tk];
            float2 x2 = *(const float2*)&As[buf][r0    ][2 * tk + 8];
            float2 x3 = *(const float2*)&As[buf][r0 + 8][2 * tk + 8];
            afr[mt][0] = pk(x0.x, x0.y);
            afr[mt][1] = pk(x1.x, x1.y);
            afr[mt][2] = pk(x2.x, x2.y);
            afr[mt][3] = pk(x3.x, x3.y);
        }
        uint32_t bfr[4][2];
#pragma unroll
        for (int nt = 0; nt < 4; nt++) {
            int c0 = wn * 32 + nt * 8 + t4;
            bfr[nt][0] = pk(Bs[buf][2 * tk    ][c0], Bs[buf][2 * tk + 1][c0]);
            bfr[nt][1] = pk(Bs[buf][2 * tk + 8][c0], Bs[buf][2 * tk + 9][c0]);
        }
#pragma unroll
        for (int mt = 0; mt < 2; mt++)
#pragma unroll
            for (int nt = 0; nt < 4; nt++)
                mma_f16(acc[mt][nt], afr[mt], bfr[nt]);
    }

#pragma unroll
    for (int mt = 0; mt < 2; mt++) {
        int r0 = block_row + wm * 32 + mt * 16 + t4;
        int r1 = r0 + 8;
        float s0 = (r0 < M) ? rsqrtf((float)(g_cur[r0] + 1)) : 0.f;
        float s1 = (r1 < M) ? rsqrtf((float)(g_cur[r1] + 1)) : 0.f;
#pragma unroll
        for (int nt = 0; nt < 4; nt++) {
            int col = wn * 32 + nt * 8 + tk * 2;
            if (r0 < M)
                *(__half2*)&g_bufh[(long)r0 * 128 + col] =
                    __float22half2_rn(make_float2(acc[mt][nt][0] * s0, acc[mt][nt][1] * s0));
            if (r1 < M)
                *(__half2*)&g_bufh[(long)r1 * 128 + col] =
                    __float22half2_rn(make_float2(acc[mt][nt][2] * s1, acc[mt][nt][3] * s1));
        }
    }
}

// ---------------------------------------------------------------- gather (R12 version — measured best)
// warp per node, fp16 input rows (8 B/lane), fp32 accumulate; dinv inline
// MODE=1: g_bufh -> g_aggh, out = fp16(relu(dinv*acc + b)*dinv)
// MODE=0: g_aggh -> g_a2h (fp16), out = dinv*acc
template <int MODE>
__global__ void k_gather(const float* __restrict__ bias, int n) {
    const __half* __restrict__ in = MODE ? g_bufh : g_aggh;
    int w = (blockIdx.x * blockDim.x + threadIdx.x) >> 5;
    int lane = threadIdx.x & 31;
    if (w >= n) return;
    int start = w * CAP;
    int raw = g_cur[w];
    int cnt = min(raw, CAP);
    float s = rsqrtf((float)(raw + 1));
    long col = (long)lane * 4;

    uint2 sv = *(const uint2*)&in[(long)w * 128 + col];   // self loop
    float2 f0 = __half22float2(*(__half2*)&sv.x);
    float2 f1 = __half22float2(*(__half2*)&sv.y);
    float4 acc = make_float4(f0.x, f0.y, f1.x, f1.y);

    int j = 0;
    for (; j + 8 <= cnt; j += 8) {
        uint2 v[8];
#pragma unroll
        for (int u = 0; u < 8; u++) {
            int sIdx = g_csr[start + j + u];
            v[u] = __ldg((const uint2*)&in[(long)sIdx * 128 + col]);
        }
#pragma unroll
        for (int u = 0; u < 8; u++) {
            float2 a = __half22float2(*(__half2*)&v[u].x);
            float2 b = __half22float2(*(__half2*)&v[u].y);
            acc.x += a.x; acc.y += a.y; acc.z += b.x; acc.w += b.y;
        }
    }
    for (; j < cnt; j++) {
        int sIdx = g_csr[start + j];
        uint2 v = __ldg((const uint2*)&in[(long)sIdx * 128 + col]);
        float2 a = __half22float2(*(__half2*)&v.x);
        float2 b = __half22float2(*(__half2*)&v.y);
        acc.x += a.x; acc.y += a.y; acc.z += b.x; acc.w += b.y;
    }

    uint2 o;
    if (MODE) {
        float4 bb = __ldg((const float4*)&bias[col]);
        float4 r;
        r.x = fmaxf(fmaf(s, acc.x, bb.x), 0.f) * s;
        r.y = fmaxf(fmaf(s, acc.y, bb.y), 0.f) * s;
        r.z = fmaxf(fmaf(s, acc.z, bb.z), 0.f) * s;
        r.w = fmaxf(fmaf(s, acc.w, bb.w), 0.f) * s;
        *(__half2*)&o.x = __float22half2_rn(make_float2(r.x, r.y));
        *(__half2*)&o.y = __float22half2_rn(make_float2(r.z, r.w));
        *(uint2*)&g_aggh[(long)w * 128 + col] = o;
    } else {
        *(__half2*)&o.x = __float22half2_rn(make_float2(acc.x * s, acc.y * s));
        *(__half2*)&o.y = __float22half2_rn(make_float2(acc.z * s, acc.w * s));
        *(uint2*)&g_a2h[(long)w * 128 + col] = o;
    }
}

// ---------------------------------------------------------------- GEMM 2
// 64x128 tile, fp16 mma, A fp16, 4-stage cp.async, 3 CTA/SM
// out_mu = a2 @ Wmu + bmu ; out_lv = a2 @ Wlv + blv   (a2 = g_a2h, pre-scaled)
__global__ void __launch_bounds__(256, 3)
k_gemm2(const float* __restrict__ Wmu, const float* __restrict__ Wlv,
        const float* __restrict__ bmu, const float* __restrict__ blv,
        float* __restrict__ out, int M) {
    const int K = 128;
    const int NS = K / KC;                  // 8
    __shared__ __half Ah[4][64][AHPAD];
    __shared__ float  Bs[4][KC][BPAD];
    __shared__ float  bias[128];
    int tid = threadIdx.x;
    int lane = tid & 31;
    int warp = tid >> 5;
    int wm = warp >> 2;             // 0..1
    int wn = warp & 3;              // 0..3
    int block_row = blockIdx.x * 64;
    int t4 = lane >> 2;
    int tk = lane & 3;

    if (tid < 128) bias[tid] = (tid < 64) ? bmu[tid] : blv[tid - 64];

    float acc[2][4][4];
#pragma unroll
    for (int i = 0; i < 2; i++)
#pragma unroll
        for (int j = 0; j < 4; j++)
#pragma unroll
            for (int c = 0; c < 4; c++) acc[i][j][c] = 0.f;

    int a_row = tid >> 1;           // 0..127 (only tid<128 used)
    int a_k   = (tid & 1) * 8;      // halves: 0 / 8 (16 B per thread)
    int b_row = tid >> 4;           // 0..15
    int b_col = (tid & 15) * 8;     // 0..120
    int gr = block_row + a_row;
    int a_size = (tid < 128 && gr < M) ? 16 : 0;
    const __half* agp = &g_a2h[(long)gr * K + a_k];
    const float* wbase = (b_col < 64) ? (Wmu + b_col) : (Wlv + (b_col - 64));

    auto issue = [&](int s) {
        int buf = s & 3;
        int k0 = s * KC;
        if (tid < 128) cpa16(s2u(&Ah[buf][a_row][a_k]), agp + k0, a_size);
        const float* wp = wbase + (long)(k0 + b_row) * 64;
        cpa16(s2u(&Bs[buf][b_row][b_col]),     wp,     16);
        cpa16(s2u(&Bs[buf][b_row][b_col + 4]), wp + 4, 16);
    };

    issue(0); CP_COMMIT();
    issue(1); CP_COMMIT();
    issue(2); CP_COMMIT();

    for (int s = 0; s < NS; s++) {
        CP_WAIT2();
        __syncthreads();
        if (s + 3 < NS) issue(s + 3);
        CP_COMMIT();

        int buf = s & 3;
        uint32_t afr[2][4];
#pragma unroll
        for (int mt = 0; mt < 2; mt++) {
            int r0 = wm * 32 + mt * 16 + t4;
            afr[mt][0] = *(const uint32_t*)&Ah[buf][r0    ][2 * tk];
            afr[mt][1] = *(const uint32_t*)&Ah[buf][r0 + 8][2 * tk];
            afr[mt][2] = *(const uint32_t*)&Ah[buf][r0    ][2 * tk + 8];
            afr[mt][3] = *(const uint32_t*)&Ah[buf][r0 + 8][2 * tk + 8];
        }
        uint32_t bfr[4][2];
#pragma unroll
        for (int nt = 0; nt < 4; nt++) {
            int c0 = wn * 32 + nt * 8 + t4;
            bfr[nt][0] = pk(Bs[buf][2 * tk    ][c0], Bs[buf][2 * tk + 1][c0]);
            bfr[nt][1] = pk(Bs[buf][2 * tk + 8][c0], Bs[buf][2 * tk + 9][c0]);
        }
#pragma unroll
        for (int mt = 0; mt < 2; mt++)
#pragma unroll
            for (int nt = 0; nt < 4; nt++)
                mma_f16(acc[mt][nt], afr[mt], bfr[nt]);
    }

    // epilogue: col<64 -> mu at out[r*64+col], else logvar at out[M*64 + r*64 + col-64]
    long lv_base = (long)M * 64;
#pragma unroll
    for (int mt = 0; mt < 2; mt++) {
        int r0 = block_row + wm * 32 + mt * 16 + t4;
        int r1 = r0 + 8;
#pragma unroll
        for (int nt = 0; nt < 4; nt++) {
            int col = wn * 32 + nt * 8 + tk * 2;
            float b0 = bias[col];
            float b1 = bias[col + 1];
            long off = (col < 64) ? (long)col : lv_base + (col - 64);
            if (r0 < M)
                *(float2*)&out[(long)r0 * 64 + off] =
                    make_float2(acc[mt][nt][0] + b0, acc[mt][nt][1] + b1);
            if (r1 < M)
                *(float2*)&out[(long)r1 * 64 + off] =
                    make_float2(acc[mt][nt][2] + b0, acc[mt][nt][3] + b1);
        }
    }
}

// ---------------------------------------------------------------- launch
extern "C" void kernel_launch(void* const* d_in, const int* in_sizes, int n_in,
                              void* d_out, int out_size) {
    const float* x   = (const float*)d_in[0];
    const int*   ei  = (const int*)d_in[1];   // JAX default x64 off: int32
    const float* W1  = (const float*)d_in[2];
    const float* b1  = (const float*)d_in[3];
    const float* Wmu = (const float*)d_in[4];
    const float* bmu = (const float*)d_in[5];
    const float* Wlv = (const float*)d_in[6];
    const float* blv = (const float*)d_in[7];
    float* out = (float*)d_out;

    int n = in_sizes[0] / 256;
    int E = in_sizes[1] / 2;
    const int* src = ei;
    const int* dst = ei + E;

    int nb_n = (n + 255) / 256;
    int nb_e4 = ((E + 3) / 4 + 255) / 256;   // 4 edges per thread
    int nb_g1 = (n + 63) / 64;               // 64-row tiles
    int nb_w = (n * 32 + 255) / 256;         // warp per node

    // dynamic smem for GEMM1 (4-stage ring: 54,272 B)
    const int g1_smem = 4 * (64 * APAD * 4 + KC * BPAD * 4);
    static bool attr_set = false;
    if (!attr_set) {
        cudaFuncSetAttribute(k_gemm1, cudaFuncAttributeMaxDynamicSharedMemorySize, g1_smem);
        attr_set = true;
    }

    // bucketed CSR (no scan, dinv computed inline by consumers)
    k_zero_cur<<<nb_n, 256>>>(n);
    k_fill    <<<nb_e4, 256>>>(src, dst, E);

    // layer 1
    k_gemm1   <<<nb_g1, 256, g1_smem>>>(x, W1, n);
    k_gather<1><<<nb_w, 256>>>(b1, n);
    // layer 2 (shared aggregation for mu/logvar)
    k_gather<0><<<nb_w, 256>>>(b1, n);
    k_gemm2   <<<nb_g1, 256>>>(Wmu, Wlv, bmu, blv, out, n);
}

// round 17
// speedup vs baseline: 1.2824x; 1.0068x over previous
#include <cuda_runtime.h>
#include <cuda_fp16.h>
#include <cstdint>

#define N_NODES 100000
#define HID 128
#define CAP 64            // bucket capacity (Poisson(16) max-degree << 64)

// Scratch (no cudaMalloc allowed)
__device__ __half g_bufh[N_NODES * HID];   // layer-1 raw GEMM rows (fp16, unscaled)
__device__ __half g_aggh[N_NODES * HID];   // layer-1 output rows (fp16, pre-scaled)
__device__ __half g_a2h [N_NODES * HID];   // layer-2 GEMM input (fp16)
__device__ float  g_dinv[N_NODES];
__device__ int    g_cur [N_NODES];         // degree counter / fill cursor
__device__ int    g_csr [N_NODES * CAP];   // bucketed src ids

// ---------------------------------------------------------------- CSR (buckets)
__global__ void k_zero_cur(int n) {
    int i = blockIdx.x * blockDim.x + threadIdx.x;
    if (i < n) g_cur[i] = 0;
}
__global__ void k_fill(const int* __restrict__ src, const int* __restrict__ dst, int E) {
    int i = blockIdx.x * blockDim.x + threadIdx.x;
    int b = i * 4;
    if (b + 4 <= E) {
        int4 d4 = *(const int4*)(dst + b);
        int4 s4 = *(const int4*)(src + b);
        int p;
        p = atomicAdd(&g_cur[d4.x], 1); if (p < CAP) g_csr[d4.x * CAP + p] = s4.x;
        p = atomicAdd(&g_cur[d4.y], 1); if (p < CAP) g_csr[d4.y * CAP + p] = s4.y;
        p = atomicAdd(&g_cur[d4.z], 1); if (p < CAP) g_csr[d4.z * CAP + p] = s4.z;
        p = atomicAdd(&g_cur[d4.w], 1); if (p < CAP) g_csr[d4.w * CAP + p] = s4.w;
    } else {
        for (int e = b; e < E; e++) {
            int d = dst[e];
            int p = atomicAdd(&g_cur[d], 1);
            if (p < CAP) g_csr[d * CAP + p] = src[e];
        }
    }
}
__global__ void k_dinv(int n) {
    int i = blockIdx.x * blockDim.x + threadIdx.x;
    if (i < n) g_dinv[i] = rsqrtf((float)(g_cur[i] + 1));   // +1 self-loop
}

// ---------------------------------------------------------------- helpers
__device__ __forceinline__ uint32_t pk(float lo, float hi) {
    uint32_t u;
    asm("cvt.rn.f16x2.f32 %0, %1, %2;" : "=r"(u) : "f"(hi), "f"(lo));
    return u;
}
__device__ __forceinline__ void mma_f16(float c[4], const uint32_t a[4], const uint32_t b[2]) {
    asm volatile(
        "mma.sync.aligned.m16n8k16.row.col.f32.f16.f16.f32 "
        "{%0,%1,%2,%3}, {%4,%5,%6,%7}, {%8,%9}, {%0,%1,%2,%3};"
        : "+f"(c[0]), "+f"(c[1]), "+f"(c[2]), "+f"(c[3])
        : "r"(a[0]), "r"(a[1]), "r"(a[2]), "r"(a[3]), "r"(b[0]), "r"(b[1]));
}
__device__ __forceinline__ uint32_t s2u(const void* p) {
    return (uint32_t)__cvta_generic_to_shared(p);
}
__device__ __forceinline__ void cpa16(uint32_t dst, const void* src, int srcsize) {
    asm volatile("cp.async.cg.shared.global [%0], [%1], 16, %2;\n"
                 :: "r"(dst), "l"(src), "r"(srcsize));
}
#define CP_COMMIT() asm volatile("cp.async.commit_group;\n" ::: "memory")
#define CP_WAIT1()  asm volatile("cp.async.wait_group 1;\n" ::: "memory")
#define CP_WAIT2()  asm volatile("cp.async.wait_group 2;\n" ::: "memory")

#define KC    16
#define APAD  20     // fp32 A row pad (floats)
#define AHPAD 24     // fp16 A row pad (halves)
#define BPAD  132    // conflict-free for k16 B frag pattern

// ---------------------------------------------------------------- GEMM 1
// 64x128 tile, 256 thr (8 warps 2m x 4n), fp16 mma, 4-stage cp.async, 3 CTA/SM
// g_bufh[r,:] = fp16((x @ W1)[r,:])   -- UNSCALED (dinv applied in gather1)
__global__ void __launch_bounds__(256, 3)
k_gemm1(const float* __restrict__ A, const float* __restrict__ W, int M) {
    const int K = 256;
    const int NS = K / KC;                  // 16
    extern __shared__ __align__(16) char dsm[];
    float (*As)[64][APAD] = (float (*)[64][APAD])dsm;                        // 4 stages
    float (*Bs)[KC][BPAD] = (float (*)[KC][BPAD])(dsm + 4 * 64 * APAD * 4);
    int tid = threadIdx.x;
    int lane = tid & 31;
    int warp = tid >> 5;
    int wm = warp >> 2;             // 0..1
    int wn = warp & 3;              // 0..3
    int block_row = blockIdx.x * 64;
    int t4 = lane >> 2;             // 0..7
    int tk = lane & 3;              // 0..3

    float acc[2][4][4];
#pragma unroll
    for (int i = 0; i < 2; i++)
#pragma unroll
        for (int j = 0; j < 4; j++)
#pragma unroll
            for (int c = 0; c < 4; c++) acc[i][j][c] = 0.f;

    int a_row = tid >> 2;           // 0..63, 4 threads/row
    int a_k   = (tid & 3) * 4;      // 0/4/8/12 (floats)
    int b_row = tid >> 4;           // 0..15
    int b_col = (tid & 15) * 8;     // 0..120
    int gr = block_row + a_row;
    int a_size = (gr < M) ? 16 : 0;
    const float* agp = &A[(long)gr * K + a_k];

    auto issue = [&](int s) {
        int buf = s & 3;
        int k0 = s * KC;
        cpa16(s2u(&As[buf][a_row][a_k]), agp + k0, a_size);
        const float* wp = &W[(k0 + b_row) * 128 + b_col];
        cpa16(s2u(&Bs[buf][b_row][b_col]),     wp,     16);
        cpa16(s2u(&Bs[buf][b_row][b_col + 4]), wp + 4, 16);
    };

    issue(0); CP_COMMIT();
    issue(1); CP_COMMIT();
    issue(2); CP_COMMIT();

    for (int s = 0; s < NS; s++) {
        CP_WAIT2();              // stage s arrived (s+1, s+2 may be in flight)
        __syncthreads();
        if (s + 3 < NS) issue(s + 3);
        CP_COMMIT();

        int buf = s & 3;
        uint32_t afr[2][4];
#pragma unroll
        for (int mt = 0; mt < 2; mt++) {
            int r0 = wm * 32 + mt * 16 + t4;
            float2 x0 = *(const float2*)&As[buf][r0    ][2 * tk];
            float2 x1 = *(const float2*)&As[buf][r0 + 8][2 * tk];
            float2 x2 = *(const float2*)&As[buf][r0    ][2 * tk + 8];
            float2 x3 = *(const float2*)&As[buf][r0 + 8][2 * tk + 8];
            afr[mt][0] = pk(x0.x, x0.y);
            afr[mt][1] = pk(x1.x, x1.y);
            afr[mt][2] = pk(x2.x, x2.y);
            afr[mt][3] = pk(x3.x, x3.y);
        }
        uint32_t bfr[4][2];
#pragma unroll
        for (int nt = 0; nt < 4; nt++) {
            int c0 = wn * 32 + nt * 8 + t4;
            bfr[nt][0] = pk(Bs[buf][2 * tk    ][c0], Bs[buf][2 * tk + 1][c0]);
            bfr[nt][1] = pk(Bs[buf][2 * tk + 8][c0], Bs[buf][2 * tk + 9][c0]);
        }
#pragma unroll
        for (int mt = 0; mt < 2; mt++)
#pragma unroll
            for (int nt = 0; nt < 4; nt++)
                mma_f16(acc[mt][nt], afr[mt], bfr[nt]);
    }

#pragma unroll
    for (int mt = 0; mt < 2; mt++) {
        int r0 = block_row + wm * 32 + mt * 16 + t4;
        int r1 = r0 + 8;
#pragma unroll
        for (int nt = 0; nt < 4; nt++) {
            int col = wn * 32 + nt * 8 + tk * 2;
            if (r0 < M)
                *(__half2*)&g_bufh[(long)r0 * 128 + col] =
                    __float22half2_rn(make_float2(acc[mt][nt][0], acc[mt][nt][1]));
            if (r1 < M)
                *(__half2*)&g_bufh[(long)r1 * 128 + col] =
                    __float22half2_rn(make_float2(acc[mt][nt][2], acc[mt][nt][3]));
        }
    }
}

// ---------------------------------------------------------------- gather
// warp per node, fp16 input rows (8 B/lane), fp32 accumulate
// MODE=1: in = g_bufh (UNSCALED): acc = sum dinv[s]*row[s] (FFMA, incl self);
//         out = fp16(relu(dinv_w*acc + b)*dinv_w) -> g_aggh
// MODE=0: in = g_aggh (pre-scaled): acc = sum row[s]; out = dinv_w*acc -> g_a2h
template <int MODE>
__global__ void k_gather(const float* __restrict__ bias, int n) {
    const __half* __restrict__ in = MODE ? g_bufh : g_aggh;
    int w = (blockIdx.x * blockDim.x + threadIdx.x) >> 5;
    int lane = threadIdx.x & 31;
    if (w >= n) return;
    int start = w * CAP;
    int raw = g_cur[w];
    int cnt = min(raw, CAP);
    float s = g_dinv[w];
    long col = (long)lane * 4;

    uint2 sv = *(const uint2*)&in[(long)w * 128 + col];   // self loop
    float2 f0 = __half22float2(*(__half2*)&sv.x);
    float2 f1 = __half22float2(*(__half2*)&sv.y);
    float4 acc;
    if (MODE) acc = make_float4(s * f0.x, s * f0.y, s * f1.x, s * f1.y);
    else      acc = make_float4(f0.x, f0.y, f1.x, f1.y);

    int j = 0;
    for (; j + 8 <= cnt; j += 8) {
        uint2 v[8];
        float dv[8];
#pragma unroll
        for (int u = 0; u < 8; u++) {
            int sIdx = g_csr[start + j + u];
            v[u] = __ldg((const uint2*)&in[(long)sIdx * 128 + col]);
            if (MODE) dv[u] = g_dinv[sIdx];
        }
#pragma unroll
        for (int u = 0; u < 8; u++) {
            float2 a = __half22float2(*(__half2*)&v[u].x);
            float2 b = __half22float2(*(__half2*)&v[u].y);
            if (MODE) {
                acc.x = fmaf(dv[u], a.x, acc.x);
                acc.y = fmaf(dv[u], a.y, acc.y);
                acc.z = fmaf(dv[u], b.x, acc.z);
                acc.w = fmaf(dv[u], b.y, acc.w);
            } else {
                acc.x += a.x; acc.y += a.y; acc.z += b.x; acc.w += b.y;
            }
        }
    }
    for (; j < cnt; j++) {
        int sIdx = g_csr[start + j];
        uint2 v = __ldg((const uint2*)&in[(long)sIdx * 128 + col]);
        float2 a = __half22float2(*(__half2*)&v.x);
        float2 b = __half22float2(*(__half2*)&v.y);
        if (MODE) {
            float dvv = g_dinv[sIdx];
            acc.x = fmaf(dvv, a.x, acc.x);
            acc.y = fmaf(dvv, a.y, acc.y);
            acc.z = fmaf(dvv, b.x, acc.z);
            acc.w = fmaf(dvv, b.y, acc.w);
        } else {
            acc.x += a.x; acc.y += a.y; acc.z += b.x; acc.w += b.y;
        }
    }

    uint2 o;
    if (MODE) {
        float4 bb = __ldg((const float4*)&bias[col]);
        float4 r;
        r.x = fmaxf(fmaf(s, acc.x, bb.x), 0.f) * s;
        r.y = fmaxf(fmaf(s, acc.y, bb.y), 0.f) * s;
        r.z = fmaxf(fmaf(s, acc.z, bb.z), 0.f) * s;
        r.w = fmaxf(fmaf(s, acc.w, bb.w), 0.f) * s;
        *(__half2*)&o.x = __float22half2_rn(make_float2(r.x, r.y));
        *(__half2*)&o.y = __float22half2_rn(make_float2(r.z, r.w));
        *(uint2*)&g_aggh[(long)w * 128 + col] = o;
    } else {
        *(__half2*)&o.x = __float22half2_rn(make_float2(acc.x * s, acc.y * s));
        *(__half2*)&o.y = __float22half2_rn(make_float2(acc.z * s, acc.w * s));
        *(uint2*)&g_a2h[(long)w * 128 + col] = o;
    }
}

// ---------------------------------------------------------------- GEMM 2 (R12 version: 128-tile, fp16 mma, A fp16, 3-stage)
__global__ void __launch_bounds__(256, 2)
k_gemm2(const float* __restrict__ Wmu, const float* __restrict__ Wlv,
        const float* __restrict__ bmu, const float* __restrict__ blv,
        float* __restrict__ out, int M) {
    const int K = 128;
    const int NS = K / KC;                  // 8
    __shared__ __half Ah[3][128][AHPAD];
    __shared__ float  Bs[3][KC][BPAD];
    __shared__ float  bias[128];
    int tid = threadIdx.x;
    int lane = tid & 31;
    int warp = tid >> 5;
    int wm = warp >> 1;
    int wn = warp & 1;
    int block_row = blockIdx.x * 128;
    int t4 = lane >> 2;
    int tk = lane & 3;

    if (tid < 128) bias[tid] = (tid < 64) ? bmu[tid] : blv[tid - 64];

    float acc[2][8][4];
#pragma unroll
    for (int i = 0; i < 2; i++)
#pragma unroll
        for (int j = 0; j < 8; j++)
#pragma unroll
            for (int c = 0; c < 4; c++) acc[i][j][c] = 0.f;

    int a_row = tid >> 1;           // 0..127
    int a_k   = (tid & 1) * 8;      // halves: 0 / 8 (16 B per thread)
    int b_row = tid >> 4;           // 0..15
    int b_col = (tid & 15) * 8;     // 0..120
    int gr = block_row + a_row;
    int a_size = (gr < M) ? 16 : 0;
    const __half* agp = &g_a2h[(long)gr * K + a_k];
    const float* wbase = (b_col < 64) ? (Wmu + b_col) : (Wlv + (b_col - 64));

    auto issue = [&](int s) {
        int buf = s % 3;
        int k0 = s * KC;
        cpa16(s2u(&Ah[buf][a_row][a_k]), agp + k0, a_size);
        const float* wp = wbase + (long)(k0 + b_row) * 64;
        cpa16(s2u(&Bs[buf][b_row][b_col]),     wp,     16);
        cpa16(s2u(&Bs[buf][b_row][b_col + 4]), wp + 4, 16);
    };

    issue(0); CP_COMMIT();
    issue(1); CP_COMMIT();

    for (int s = 0; s < NS; s++) {
        CP_WAIT1();
        __syncthreads();
        if (s + 2 < NS) issue(s + 2);
        CP_COMMIT();

        int buf = s % 3;
        uint32_t afr[2][4];
#pragma unroll
        for (int mt = 0; mt < 2; mt++) {
            int r0 = wm * 32 + mt * 16 + t4;
            afr[mt][0] = *(const uint32_t*)&Ah[buf][r0    ][2 * tk];
            afr[mt][1] = *(const uint32_t*)&Ah[buf][r0 + 8][2 * tk];
            afr[mt][2] = *(const uint32_t*)&Ah[buf][r0    ][2 * tk + 8];
            afr[mt][3] = *(const uint32_t*)&Ah[buf][r0 + 8][2 * tk + 8];
        }
        uint32_t bfr[8][2];
#pragma unroll
        for (int nt = 0; nt < 8; nt++) {
            int c0 = wn * 64 + nt * 8 + t4;
            bfr[nt][0] = pk(Bs[buf][2 * tk    ][c0], Bs[buf][2 * tk + 1][c0]);
            bfr[nt][1] = pk(Bs[buf][2 * tk + 8][c0], Bs[buf][2 * tk + 9][c0]);
        }
#pragma unroll
        for (int mt = 0; mt < 2; mt++)
#pragma unroll
            for (int nt = 0; nt < 8; nt++)
                mma_f16(acc[mt][nt], afr[mt], bfr[nt]);
    }

    // epilogue: wn=0 -> mu at out[r*64+c], wn=1 -> logvar at out[M*64 + r*64 + c]
    float* base = out + (wn ? (long)M * 64 : 0);
#pragma unroll
    for (int mt = 0; mt < 2; mt++) {
        int r0 = block_row + wm * 32 + mt * 16 + t4;
        int r1 = r0 + 8;
#pragma unroll
        for (int nt = 0; nt < 8; nt++) {
            int c = nt * 8 + tk * 2;            // 0..63 within the 64-wide half
            float b0 = bias[wn * 64 + c];
            float b1 = bias[wn * 64 + c + 1];
            if (r0 < M)
                *(float2*)&base[(long)r0 * 64 + c] =
                    make_float2(acc[mt][nt][0] + b0, acc[mt][nt][1] + b1);
            if (r1 < M)
                *(float2*)&base[(long)r1 * 64 + c] =
                    make_float2(acc[mt][nt][2] + b0, acc[mt][nt][3] + b1);
        }
    }
}

// ---------------------------------------------------------------- launch
extern "C" void kernel_launch(void* const* d_in, const int* in_sizes, int n_in,
                              void* d_out, int out_size) {
    const float* x   = (const float*)d_in[0];
    const int*   ei  = (const int*)d_in[1];   // JAX default x64 off: int32
    const float* W1  = (const float*)d_in[2];
    const float* b1  = (const float*)d_in[3];
    const float* Wmu = (const float*)d_in[4];
    const float* bmu = (const float*)d_in[5];
    const float* Wlv = (const float*)d_in[6];
    const float* blv = (const float*)d_in[7];
    float* out = (float*)d_out;

    int n = in_sizes[0] / 256;
    int E = in_sizes[1] / 2;
    const int* src = ei;
    const int* dst = ei + E;

    int nb_n = (n + 255) / 256;
    int nb_e4 = ((E + 3) / 4 + 255) / 256;   // 4 edges per thread
    int nb_g1 = (n + 63) / 64;               // 64-row tiles (GEMM1)
    int nb_g2 = (n + 127) / 128;             // 128-row tiles (GEMM2)
    int nb_w = (n * 32 + 255) / 256;         // warp per node

    // dynamic smem for GEMM1 (4-stage ring: 54,272 B)
    const int g1_smem = 4 * (64 * APAD * 4 + KC * BPAD * 4);

    // One-time setup: func attr + side stream + fork/join events
    static cudaStream_t s_csr = nullptr;
    static cudaEvent_t  ev_fork = nullptr, ev_join = nullptr;
    if (!s_csr) {
        cudaFuncSetAttribute(k_gemm1, cudaFuncAttributeMaxDynamicSharedMemorySize, g1_smem);
        cudaStreamCreateWithFlags(&s_csr, cudaStreamNonBlocking);
        cudaEventCreateWithFlags(&ev_fork, cudaEventDisableTiming);
        cudaEventCreateWithFlags(&ev_join, cudaEventDisableTiming);
    }

    // fork: CSR build (zero -> fill -> dinv) on side stream, concurrent with GEMM1
    cudaEventRecord(ev_fork, 0);
    cudaStreamWaitEvent(s_csr, ev_fork, 0);
    k_zero_cur<<<nb_n, 256, 0, s_csr>>>(n);
    k_fill    <<<nb_e4, 256, 0, s_csr>>>(src, dst, E);
    k_dinv    <<<nb_n, 256, 0, s_csr>>>(n);
    cudaEventRecord(ev_join, s_csr);

    // GEMM1 (independent of CSR now — writes unscaled rows)
    k_gemm1   <<<nb_g1, 256, g1_smem>>>(x, W1, n);

    // join: gathers need both GEMM1 and CSR
    cudaStreamWaitEvent(0, ev_join, 0);
    k_gather<1><<<nb_w, 256>>>(b1, n);
    k_gather<0><<<nb_w, 256>>>(b1, n);
    k_gemm2   <<<nb_g2, 256>>>(Wmu, Wlv, bmu, blv, out, n);
}